// round 2
// baseline (speedup 1.0000x reference)
#include <cuda_runtime.h>
#include <cstdint>

#define NPTS 4096
#define BATCH 16
#define MCTR 1024
#define KNBR 64
#define FDIM 64
#define H1D  64
#define H2D  64
#define OUTD 128
#define R2C  0.04f
#define CAND_CAP 2048

// ---------------- device scratch (no allocations allowed) ----------------
__device__ int   g_idx[BATCH * MCTR];
__device__ float g_feat[(size_t)BATCH * NPTS * H1D];   // x @ W1[0:64,:]  (16 MB)

// =========================================================================
// FPS: one block per batch, 512 threads, 8 points per thread (strided).
// Matches reference: dists=min(dists, d(p,last)); next=argmax (first occ).
// Emits idx[m]=last BEFORE update, exactly like the lax.scan.
// =========================================================================
struct FPSSmem {
    float px[NPTS], py[NPTS], pz[NPTS];
    float bv[16];
    int   bi[16];
    int   last;
};

__global__ __launch_bounds__(512) void fps_kernel(
    const float* __restrict__ pos, float* __restrict__ pos_s_out)
{
    extern __shared__ unsigned char fsm_raw[];
    FPSSmem& s = *reinterpret_cast<FPSSmem*>(fsm_raw);

    int b = blockIdx.x;
    const float* pb = pos + (size_t)b * NPTS * 3;

    int tid = threadIdx.x;
    float px[8], py[8], pz[8], dst[8];
#pragma unroll
    for (int u = 0; u < 8; u++) {
        int i = tid + u * 512;
        float x = pb[i * 3 + 0], y = pb[i * 3 + 1], z = pb[i * 3 + 2];
        s.px[i] = x; s.py[i] = y; s.pz[i] = z;
        px[u] = x; py[u] = y; pz[u] = z;
        dst[u] = 1e10f;
    }
    __syncthreads();

    int   last = 0;
    float lx = s.px[0], ly = s.py[0], lz = s.pz[0];

    for (int m = 0; m < MCTR; m++) {
        if (tid == 0) {
            g_idx[b * MCTR + m] = last;
            float* po = pos_s_out + ((size_t)(b * MCTR + m)) * 3;
            po[0] = lx; po[1] = ly; po[2] = lz;
        }
        float bv = -1.0f; int bi = 0;
#pragma unroll
        for (int u = 0; u < 8; u++) {
            float dx = px[u] - lx, dy = py[u] - ly, dz = pz[u] - lz;
            float d  = fmaf(dx, dx, fmaf(dy, dy, dz * dz));
            float nd = fminf(dst[u], d);
            dst[u] = nd;
            int gi = tid + u * 512;
            if (nd > bv) { bv = nd; bi = gi; }   // ascending gi -> first occurrence kept
        }
        // warp reduce (max val, min idx on ties)
#pragma unroll
        for (int off = 16; off; off >>= 1) {
            float ov = __shfl_down_sync(0xffffffffu, bv, off);
            int   oi = __shfl_down_sync(0xffffffffu, bi, off);
            if (ov > bv || (ov == bv && oi < bi)) { bv = ov; bi = oi; }
        }
        if ((tid & 31) == 0) { s.bv[tid >> 5] = bv; s.bi[tid >> 5] = bi; }
        __syncthreads();
        if (tid < 32) {
            float v = (tid < 16) ? s.bv[tid] : -2.0f;
            int   i = (tid < 16) ? s.bi[tid] : 0x7fffffff;
#pragma unroll
            for (int off = 8; off; off >>= 1) {
                float ov = __shfl_down_sync(0xffffffffu, v, off);
                int   oi = __shfl_down_sync(0xffffffffu, i, off);
                if (ov > v || (ov == v && oi < i)) { v = ov; i = oi; }
            }
            if (tid == 0) s.last = i;
        }
        __syncthreads();
        last = s.last;
        lx = s.px[last]; ly = s.py[last]; lz = s.pz[last];
    }
}

// =========================================================================
// g = x @ W1[0:64,:]   (no bias; bias added in layer-1 of center kernel)
// block: 128 threads handles 32 rows; thread = (row=tid/4, 16 channels)
// =========================================================================
__global__ __launch_bounds__(128) void feat_kernel(
    const float* __restrict__ x, const float* __restrict__ W1)
{
    __shared__ float s_x[32][64];
    __shared__ float s_w[64][64];
    int tid = threadIdx.x;
    size_t rbase = (size_t)blockIdx.x * 32;

    for (int i = tid; i < 64 * 64; i += 128) s_w[i >> 6][i & 63] = W1[i];
    for (int i = tid; i < 32 * 64; i += 128) s_x[i >> 6][i & 63] = x[rbase * 64 + i];
    __syncthreads();

    int r = tid >> 2, q = tid & 3;
    float acc[16];
#pragma unroll
    for (int c = 0; c < 16; c++) acc[c] = 0.f;
    for (int k = 0; k < 64; k++) {
        float xv = s_x[r][k];
#pragma unroll
        for (int c = 0; c < 16; c++) acc[c] = fmaf(xv, s_w[k][q * 16 + c], acc[c]);
    }
    float* go = g_feat + (rbase + r) * 64 + q * 16;
#pragma unroll
    for (int c = 0; c < 16; c++) go[c] = acc[c];
}

// =========================================================================
// Per-center kernel: ball query (exact top-K by (d2, idx)) + MLP + max pool
// =========================================================================
struct CKSmem {
    union {
        unsigned long long cand[CAND_CAP];   // 16 KB (selection phase)
        float W2s[64 * 64];                  // 16 KB (MLP phase)
    } u;
    float W3s[64 * 128];      // 32 KB
    float h1s[32][68];        // padded rows
    float h2s[32][68];
    float red[8][128];
    float W1bs[3][64];
    float b1s[64], b2s[64], b3s[128];
    float rel[KNBR][3];
    int   nbr[KNBR];
    float ctr[3];
    int   cnt;
    int   nvalid;
};

__global__ __launch_bounds__(128) void center_kernel(
    const float* __restrict__ pos,
    const float* __restrict__ W1, const float* __restrict__ b1,
    const float* __restrict__ W2, const float* __restrict__ b2,
    const float* __restrict__ W3, const float* __restrict__ b3,
    float* __restrict__ out)
{
    extern __shared__ unsigned char smraw[];
    CKSmem& s = *reinterpret_cast<CKSmem*>(smraw);

    int tid = threadIdx.x;
    int blk = blockIdx.x;
    int b = blk >> 10;
    const float* pb = pos + (size_t)b * NPTS * 3;

    if (tid == 0) {
        int ci = g_idx[blk];
        s.ctr[0] = pb[ci * 3 + 0];
        s.ctr[1] = pb[ci * 3 + 1];
        s.ctr[2] = pb[ci * 3 + 2];
        s.cnt = 0;
    }
    __syncthreads();
    float cx = s.ctr[0], cy = s.ctr[1], cz = s.ctr[2];

    // ---- phase 1: candidates within R^2, key = d2_bits<<32 | idx ----
    for (int i = tid; i < NPTS; i += 128) {
        float dx = pb[i * 3 + 0] - cx;
        float dy = pb[i * 3 + 1] - cy;
        float dz = pb[i * 3 + 2] - cz;
        float d2 = fmaf(dx, dx, fmaf(dy, dy, dz * dz));
        if (d2 <= R2C) {
            int p = atomicAdd(&s.cnt, 1);
            if (p < CAND_CAP)
                s.u.cand[p] = ((unsigned long long)__float_as_uint(d2) << 32) | (unsigned)i;
        }
    }
    __syncthreads();
    int n  = min(s.cnt, CAND_CAP);
    int nv = min(n, KNBR);

    // ---- phase 2: if >K candidates, bitonic sort -> K smallest (d2, idx) ----
    if (n > KNBR) {
        int P = 1; while (P < n) P <<= 1;
        for (int i = n + tid; i < P; i += 128) s.u.cand[i] = ~0ull;
        __syncthreads();
        for (int k = 2; k <= P; k <<= 1)
            for (int j = k >> 1; j; j >>= 1) {
                for (int i = tid; i < P; i += 128) {
                    int ixj = i ^ j;
                    if (ixj > i) {
                        unsigned long long a = s.u.cand[i], c = s.u.cand[ixj];
                        bool up = ((i & k) == 0);
                        if ((a > c) == up) { s.u.cand[i] = c; s.u.cand[ixj] = a; }
                    }
                }
                __syncthreads();
            }
    }

    // ---- extract neighbors + rel ----
    if (tid < KNBR) {
        if (tid < nv) {
            int j = (int)(s.u.cand[tid] & 0xffffffffu);
            s.nbr[tid]    = j;
            s.rel[tid][0] = pb[j * 3 + 0] - cx;
            s.rel[tid][1] = pb[j * 3 + 1] - cy;
            s.rel[tid][2] = pb[j * 3 + 2] - cz;
        } else {
            s.nbr[tid] = 0;
            s.rel[tid][0] = 0.f; s.rel[tid][1] = 0.f; s.rel[tid][2] = 0.f;
        }
    }
    if (tid == 0) s.nvalid = nv;
    __syncthreads();   // cand no longer needed; union becomes W2s

    // ---- load weights to smem ----
    for (int i = tid; i < 64 * 64; i += 128)  s.u.W2s[i] = W2[i];
    for (int i = tid; i < 64 * 128; i += 128) s.W3s[i]   = W3[i];
    for (int i = tid; i < 3 * 64; i += 128)   s.W1bs[i >> 6][i & 63] = W1[64 * 64 + i];
    if (tid < 64)  { s.b1s[tid] = b1[tid]; s.b2s[tid] = b2[tid]; }
    if (tid < 128) s.b3s[tid] = b3[tid];
    __syncthreads();

    int nvalid = s.nvalid;
    float mx[8];
#pragma unroll
    for (int c = 0; c < 8; c++) mx[c] = -1e30f;

    for (int grp = 0; grp < 2; grp++) {
        int nbase = grp * 32;
        if (nbase >= nvalid) break;

        // ---- h1: thread = (neighbor nl=tid/4, 16 channels) ----
        {
            int nl = tid >> 2, q = tid & 3;
            int slot = nbase + nl;
            if (slot >= KNBR) slot = 0;
            int j = s.nbr[slot];
            const float* gr = g_feat + ((size_t)(b * NPTS + j)) * 64 + q * 16;
            float rx = s.rel[slot][0], ry = s.rel[slot][1], rz = s.rel[slot][2];
#pragma unroll
            for (int c = 0; c < 16; c++) {
                int ch = q * 16 + c;
                float v = gr[c];
                v = fmaf(rx, s.W1bs[0][ch], v);
                v = fmaf(ry, s.W1bs[1][ch], v);
                v = fmaf(rz, s.W1bs[2][ch], v);
                v += s.b1s[ch];
                s.h1s[nl][ch] = fmaxf(v, 0.f);
            }
        }
        __syncthreads();

        // ---- h2: thread = (8 channels coct, 2 neighbors) ----
        {
            int coct = tid & 7, npair = tid >> 3;
            int n0 = 2 * npair, n1 = n0 + 1;
            float acc0[8], acc1[8];
#pragma unroll
            for (int c = 0; c < 8; c++) { acc0[c] = 0.f; acc1[c] = 0.f; }
            for (int k = 0; k < 64; k += 4) {
                float4 h0 = *reinterpret_cast<const float4*>(&s.h1s[n0][k]);
                float4 h1 = *reinterpret_cast<const float4*>(&s.h1s[n1][k]);
                float ha[4] = {h0.x, h0.y, h0.z, h0.w};
                float hb[4] = {h1.x, h1.y, h1.z, h1.w};
#pragma unroll
                for (int kk = 0; kk < 4; kk++) {
                    const float4 wlo = *reinterpret_cast<const float4*>(&s.u.W2s[(k + kk) * 64 + coct * 8]);
                    const float4 whi = *reinterpret_cast<const float4*>(&s.u.W2s[(k + kk) * 64 + coct * 8 + 4]);
                    float wv[8] = {wlo.x, wlo.y, wlo.z, wlo.w, whi.x, whi.y, whi.z, whi.w};
#pragma unroll
                    for (int c = 0; c < 8; c++) {
                        acc0[c] = fmaf(ha[kk], wv[c], acc0[c]);
                        acc1[c] = fmaf(hb[kk], wv[c], acc1[c]);
                    }
                }
            }
#pragma unroll
            for (int c = 0; c < 8; c++) {
                int ch = coct * 8 + c;
                s.h2s[n0][ch] = fmaxf(acc0[c] + s.b2s[ch], 0.f);
                s.h2s[n1][ch] = fmaxf(acc1[c] + s.b2s[ch], 0.f);
            }
        }
        __syncthreads();

        // ---- h3 + max: thread = (8 channels of 128, 4 neighbors) ----
        {
            int c16 = tid & 15, nq = tid >> 4;
            int nb0 = 4 * nq;
            float acc[4][8];
#pragma unroll
            for (int sN = 0; sN < 4; sN++)
#pragma unroll
                for (int c = 0; c < 8; c++) acc[sN][c] = 0.f;

            for (int k = 0; k < 64; k += 4) {
                float hv[4][4];
#pragma unroll
                for (int sN = 0; sN < 4; sN++) {
                    float4 h = *reinterpret_cast<const float4*>(&s.h2s[nb0 + sN][k]);
                    hv[sN][0] = h.x; hv[sN][1] = h.y; hv[sN][2] = h.z; hv[sN][3] = h.w;
                }
#pragma unroll
                for (int kk = 0; kk < 4; kk++) {
                    const float4 wlo = *reinterpret_cast<const float4*>(&s.W3s[(k + kk) * 128 + c16 * 8]);
                    const float4 whi = *reinterpret_cast<const float4*>(&s.W3s[(k + kk) * 128 + c16 * 8 + 4]);
                    float wv[8] = {wlo.x, wlo.y, wlo.z, wlo.w, whi.x, whi.y, whi.z, whi.w};
#pragma unroll
                    for (int sN = 0; sN < 4; sN++)
#pragma unroll
                        for (int c = 0; c < 8; c++)
                            acc[sN][c] = fmaf(hv[sN][kk], wv[c], acc[sN][c]);
                }
            }
#pragma unroll
            for (int sN = 0; sN < 4; sN++) {
                if (nbase + nb0 + sN < nvalid) {
#pragma unroll
                    for (int c = 0; c < 8; c++) mx[c] = fmaxf(mx[c], acc[sN][c]);
                }
            }
        }
        __syncthreads();   // before next group's h1 overwrite
    }

    // ---- cross-thread max over the 8 neighbor-quad groups ----
    {
        int c16 = tid & 15, nq = tid >> 4;
#pragma unroll
        for (int c = 0; c < 8; c++) s.red[nq][c16 * 8 + c] = mx[c];
    }
    __syncthreads();
    {
        float v = s.red[0][tid];
#pragma unroll
        for (int w = 1; w < 8; w++) v = fmaxf(v, s.red[w][tid]);
        out[(size_t)blk * OUTD + tid] = v + s.b3s[tid];
    }
}

// =========================================================================
extern "C" void kernel_launch(void* const* d_in, const int* in_sizes, int n_in,
                              void* d_out, int out_size)
{
    const float* x   = (const float*)d_in[0];
    const float* pos = (const float*)d_in[1];
    const float* W1  = (const float*)d_in[2];
    const float* b1  = (const float*)d_in[3];
    const float* W2  = (const float*)d_in[4];
    const float* b2  = (const float*)d_in[5];
    const float* W3  = (const float*)d_in[6];
    const float* b3  = (const float*)d_in[7];

    float* out       = (float*)d_out;                          // [B, M, OUT]
    float* pos_s_out = out + (size_t)BATCH * MCTR * OUTD;      // [B, M, 3]

    // Idempotent, host-side, non-stream API: safe under graph capture,
    // no static guard needed.
    cudaFuncSetAttribute(center_kernel,
                         cudaFuncAttributeMaxDynamicSharedMemorySize,
                         (int)sizeof(CKSmem));
    cudaFuncSetAttribute(fps_kernel,
                         cudaFuncAttributeMaxDynamicSharedMemorySize,
                         (int)sizeof(FPSSmem));

    feat_kernel<<<(BATCH * NPTS) / 32, 128>>>(x, W1);
    fps_kernel<<<BATCH, 512, sizeof(FPSSmem)>>>(pos, pos_s_out);
    center_kernel<<<BATCH * MCTR, 128, sizeof(CKSmem)>>>(
        pos, W1, b1, W2, b2, W3, b3, out);
}